// round 8
// baseline (speedup 1.0000x reference)
#include <cuda_runtime.h>
#include <cuda_bf16.h>
#include <cstdint>
#include <math.h>

// ---------------- problem dims ----------------
#define NTOK 4096   // B*S = 2*2048
#define HIDD 4096
#define BOTD 64
#define RD   48
#define NSL  1024
#define KS   8
#define VBD  256
#define H4   1024   // HID/4
#define SPLITK 8

// ---------------- device scratch ----------------
__device__ __nv_bfloat16 g_hb[NTOK * HIDD];          // 32 MB
__device__ __nv_bfloat16 g_Wu1b[H4 * HIDD];          // 8 MB
__device__ __nv_bfloat16 g_Wqb[BOTD * HIDD];         // 0.5 MB
__device__ __nv_bfloat16 g_avb[NSL * HIDD];          // 8 MB
__device__ __nv_bfloat16 g_Wvdb[VBD * HIDD];         // 2 MB
__device__ __nv_bfloat16 g_Wvub[HIDD * VBD];         // 2 MB
__device__ float g_query[NTOK * BOTD];               // 1 MB
__device__ float g_rq[NTOK * RD];
__device__ float g_rk[NSL * RD];
__device__ float g_scores[NTOK * NSL];               // 16 MB
__device__ float g_AVd[NSL * VBD];                   // 1 MB
__device__ float g_AVd_part[SPLITK * NSL * VBD];     // 8 MB
__device__ float g_query_part[SPLITK * NTOK * BOTD]; // 8 MB
__device__ __nv_bfloat16 g_tb[NTOK * VBD];           // 2 MB
__device__ float g_partial[16 * NTOK];               // deterministic Wu2-dot partials
__device__ float g_logvar[NTOK];
__device__ float g_gate[NTOK];

// ---------------- small helpers ----------------
__device__ __forceinline__ uint32_t smem_u32(const void* p) {
    return (uint32_t)__cvta_generic_to_shared(p);
}
__device__ __forceinline__ void cp_async16(void* dst, const void* src) {
    asm volatile("cp.async.cg.shared.global [%0], [%1], 16;\n"
                 :: "r"(smem_u32(dst)), "l"(src));
}
__device__ __forceinline__ void cp_commit() { asm volatile("cp.async.commit_group;\n"); }
template <int N> __device__ __forceinline__ void cp_wait() {
    asm volatile("cp.async.wait_group %0;\n" :: "n"(N));
}
__device__ __forceinline__ float gelu_tanh(float x) {
    float x3 = x * x * x;
    return 0.5f * x * (1.0f + tanhf(0.7978845608028654f * (x + 0.044715f * x3)));
}
__device__ __forceinline__ float sigmoidf(float x) { return 1.0f / (1.0f + expf(-x)); }

// ---------------- batched bf16 convert (5 weight tensors in one launch) ----------------
__global__ void __launch_bounds__(256) cvt_all_kernel(
    const float* __restrict__ s0, __nv_bfloat16* __restrict__ d0, int n0,
    const float* __restrict__ s1, __nv_bfloat16* __restrict__ d1, int n1,
    const float* __restrict__ s2, __nv_bfloat16* __restrict__ d2, int n2,
    const float* __restrict__ s3, __nv_bfloat16* __restrict__ d3, int n3,
    const float* __restrict__ s4, __nv_bfloat16* __restrict__ d4, int n4) {
    int i = blockIdx.x * blockDim.x + threadIdx.x;
    const float* src; __nv_bfloat16* dst; int local;
    if (i < n0)                       { src = s0; dst = d0; local = i; }
    else if (i < n0 + n1)             { src = s1; dst = d1; local = i - n0; }
    else if (i < n0 + n1 + n2)        { src = s2; dst = d2; local = i - n0 - n1; }
    else if (i < n0 + n1 + n2 + n3)   { src = s3; dst = d3; local = i - n0 - n1 - n2; }
    else if (i < n0 + n1 + n2 + n3 + n4) { src = s4; dst = d4; local = i - n0 - n1 - n2 - n3; }
    else return;
    float4 v = ((const float4*)src)[local];
    union { __nv_bfloat162 b2[2]; uint2 u; } p;
    p.b2[0] = __floats2bfloat162_rn(v.x, v.y);
    p.b2[1] = __floats2bfloat162_rn(v.z, v.w);
    ((uint2*)dst)[local] = p.u;
}

// ---------------- per-token variance + h->bf16 (fused) ----------------
__global__ void __launch_bounds__(256) var_cvt_kernel(const float* __restrict__ h,
                                                      __nv_bfloat16* __restrict__ hb,
                                                      float* __restrict__ logvar) {
    const int t = blockIdx.x, tid = threadIdx.x;
    const float4* row = (const float4*)(h + (size_t)t * HIDD);
    uint2* drow = (uint2*)(hb + (size_t)t * HIDD);
    float s = 0.f, ss = 0.f;
    for (int i = tid; i < HIDD / 4; i += 256) {
        float4 v = row[i];
        s += (v.x + v.y) + (v.z + v.w);
        ss += v.x * v.x + v.y * v.y + v.z * v.z + v.w * v.w;
        union { __nv_bfloat162 b2[2]; uint2 u; } p;
        p.b2[0] = __floats2bfloat162_rn(v.x, v.y);
        p.b2[1] = __floats2bfloat162_rn(v.z, v.w);
        drow[i] = p.u;
    }
    __shared__ float rs[256], rss[256];
    rs[tid] = s; rss[tid] = ss;
    __syncthreads();
    for (int st = 128; st > 0; st >>= 1) {
        if (tid < st) { rs[tid] += rs[tid + st]; rss[tid] += rss[tid + st]; }
        __syncthreads();
    }
    if (tid == 0) {
        float mean = rs[0] * (1.f / HIDD);
        float var = rss[0] * (1.f / HIDD) - mean * mean;
        logvar[t] = log1pf(var);
    }
}

// ---------------- bf16 TN GEMM, 3-stage cp.async pipeline, optional split-K ----------------
// C[M,N] = A[M,K] * B[N,K]^T  over K-slice blockIdx.z (slice size Kd/gridDim.z)
// EPI 0: store C (f32) at slice offset blockIdx.z*M*N
// EPI 1: partial[(bx*2+wn)*NTOK+row] = sum_n Wu2[n]*gelu(acc+bu1[n]) (ep0=bu1, ep1=Wu2, ep2=partial)
// EPI 2: C[r,c] = ep0[r,c] + ep1[r]*acc                              (ep0=h, ep1=gate, C=out)
template <int BM, int BN, int EPI>
__global__ void __launch_bounds__(256)
gemm_tn(const __nv_bfloat16* __restrict__ A, const __nv_bfloat16* __restrict__ B,
        float* __restrict__ C, int M, int N, int Kd,
        const float* __restrict__ ep0, const float* __restrict__ ep1,
        float* __restrict__ ep2) {
    constexpr int BK = 32;
    constexpr int LDSW = BK + 8;           // 40 bf16 row pitch -> staggered banks
    constexpr int TM = BM / 4, TN = BN / 2;
    constexpr int MI = TM / 16, NI = TN / 8;

    extern __shared__ __align__(16) char dynsmem[];
    __nv_bfloat16* sAr = (__nv_bfloat16*)dynsmem;            // [3][BM][LDSW]
    __nv_bfloat16* sBr = sAr + 3 * BM * LDSW;                // [3][BN][LDSW]

    const int tid = threadIdx.x;
    const int warp = tid >> 5, lane = tid & 31;
    const int wm = warp & 3, wn = warp >> 2;   // 4x2 warp grid
    const int m0 = blockIdx.y * BM, n0 = blockIdx.x * BN;

    const int Kslice = Kd / gridDim.z;
    const int kbase = blockIdx.z * Kslice;
    const int KT = Kslice / BK;

    float acc[MI][NI][4];
#pragma unroll
    for (int i = 0; i < MI; ++i)
#pragma unroll
        for (int j = 0; j < NI; ++j) {
            acc[i][j][0] = acc[i][j][1] = acc[i][j][2] = acc[i][j][3] = 0.f;
        }

    auto load_tile = [&](int kt, int buf) {
        const int k0 = kbase + kt * BK;
        for (int c = tid; c < BM * 4; c += 256) {
            int r = c >> 2, kc = (c & 3) * 8;
            cp_async16(&sAr[(buf * BM + r) * LDSW + kc], A + (size_t)(m0 + r) * Kd + k0 + kc);
        }
        for (int c = tid; c < BN * 4; c += 256) {
            int r = c >> 2, kc = (c & 3) * 8;
            cp_async16(&sBr[(buf * BN + r) * LDSW + kc], B + (size_t)(n0 + r) * Kd + k0 + kc);
        }
    };

    load_tile(0, 0);
    cp_commit();
    load_tile(1, 1);
    cp_commit();

    for (int kt = 0; kt < KT; ++kt) {
        const int buf = kt % 3;
        if (kt + 1 < KT) cp_wait<1>(); else cp_wait<0>();
        __syncthreads();

#pragma unroll
        for (int kk = 0; kk < BK; kk += 16) {
            uint32_t af[MI][4];
#pragma unroll
            for (int mi = 0; mi < MI; ++mi) {
                uint32_t a = smem_u32(&sAr[(buf * BM + wm * TM + mi * 16 + (lane & 15)) * LDSW
                                           + kk + (lane >> 4) * 8]);
                asm volatile("ldmatrix.sync.aligned.m8n8.x4.shared.b16 {%0,%1,%2,%3}, [%4];"
                             : "=r"(af[mi][0]), "=r"(af[mi][1]),
                               "=r"(af[mi][2]), "=r"(af[mi][3]) : "r"(a));
            }
            uint32_t bfr[NI][2];
#pragma unroll
            for (int ni = 0; ni < NI; ++ni) {
                uint32_t a = smem_u32(&sBr[(buf * BN + wn * TN + ni * 8 + (lane & 7)) * LDSW
                                           + kk + ((lane >> 3) & 1) * 8]);
                asm volatile("ldmatrix.sync.aligned.m8n8.x2.shared.b16 {%0,%1}, [%2];"
                             : "=r"(bfr[ni][0]), "=r"(bfr[ni][1]) : "r"(a));
            }
#pragma unroll
            for (int mi = 0; mi < MI; ++mi)
#pragma unroll
                for (int ni = 0; ni < NI; ++ni)
                    asm volatile(
                        "mma.sync.aligned.m16n8k16.row.col.f32.bf16.bf16.f32 "
                        "{%0,%1,%2,%3}, {%4,%5,%6,%7}, {%8,%9}, {%0,%1,%2,%3};"
                        : "+f"(acc[mi][ni][0]), "+f"(acc[mi][ni][1]),
                          "+f"(acc[mi][ni][2]), "+f"(acc[mi][ni][3])
                        : "r"(af[mi][0]), "r"(af[mi][1]), "r"(af[mi][2]), "r"(af[mi][3]),
                          "r"(bfr[ni][0]), "r"(bfr[ni][1]));
        }
        __syncthreads();
        if (kt + 2 < KT) {
            load_tile(kt + 2, (kt + 2) % 3);
            cp_commit();
        }
    }

    const int row0 = m0 + wm * TM;
    if (EPI == 0) {
        float* Cs = C + (size_t)blockIdx.z * M * N;
#pragma unroll
        for (int mi = 0; mi < MI; ++mi) {
            int r = row0 + mi * 16 + (lane >> 2);
#pragma unroll
            for (int ni = 0; ni < NI; ++ni) {
                int c = n0 + wn * TN + ni * 8 + (lane & 3) * 2;
                *(float2*)&Cs[(size_t)r * N + c] = make_float2(acc[mi][ni][0], acc[mi][ni][1]);
                *(float2*)&Cs[(size_t)(r + 8) * N + c] = make_float2(acc[mi][ni][2], acc[mi][ni][3]);
            }
        }
    } else if (EPI == 1) {
        // one writer per (blockIdx.x, wn, row) -> deterministic
        float* pout = ep2 + (size_t)(blockIdx.x * 2 + wn) * NTOK;
#pragma unroll
        for (int mi = 0; mi < MI; ++mi) {
            float p0 = 0.f, p1 = 0.f;
#pragma unroll
            for (int ni = 0; ni < NI; ++ni) {
                int c = n0 + wn * TN + ni * 8 + (lane & 3) * 2;
                float b0 = ep0[c], b1 = ep0[c + 1];
                float w0 = ep1[c], w1 = ep1[c + 1];
                p0 += gelu_tanh(acc[mi][ni][0] + b0) * w0 + gelu_tanh(acc[mi][ni][1] + b1) * w1;
                p1 += gelu_tanh(acc[mi][ni][2] + b0) * w0 + gelu_tanh(acc[mi][ni][3] + b1) * w1;
            }
            p0 += __shfl_xor_sync(0xffffffffu, p0, 1);
            p0 += __shfl_xor_sync(0xffffffffu, p0, 2);
            p1 += __shfl_xor_sync(0xffffffffu, p1, 1);
            p1 += __shfl_xor_sync(0xffffffffu, p1, 2);
            if ((lane & 3) == 0) {
                pout[row0 + mi * 16 + (lane >> 2)] = p0;
                pout[row0 + mi * 16 + (lane >> 2) + 8] = p1;
            }
        }
    } else {  // EPI == 2
#pragma unroll
        for (int mi = 0; mi < MI; ++mi) {
            int r = row0 + mi * 16 + (lane >> 2);
            float g0 = ep1[r], g1 = ep1[r + 8];
#pragma unroll
            for (int ni = 0; ni < NI; ++ni) {
                int c = n0 + wn * TN + ni * 8 + (lane & 3) * 2;
                size_t i0 = (size_t)r * N + c;
                float2 h0 = *(const float2*)&ep0[i0];
                *(float2*)&C[i0] = make_float2(h0.x + g0 * acc[mi][ni][0],
                                               h0.y + g0 * acc[mi][ni][1]);
                size_t i1 = (size_t)(r + 8) * N + c;
                float2 h1 = *(const float2*)&ep0[i1];
                *(float2*)&C[i1] = make_float2(h1.x + g1 * acc[mi][ni][2],
                                               h1.y + g1 * acc[mi][ni][3]);
            }
        }
    }
}

// ---------------- split-K reduction for AVd and query (fixed order, deterministic) ----------------
__global__ void __launch_bounds__(256) reduce_parts_kernel(
    const float* __restrict__ pa, float* __restrict__ oa, int na,
    const float* __restrict__ pb, float* __restrict__ ob, int nb) {
    int i = blockIdx.x * blockDim.x + threadIdx.x;
    if (i < na) {
        float s = 0.f;
#pragma unroll
        for (int z = 0; z < SPLITK; ++z) s += pa[(size_t)z * na + i];
        oa[i] = s;
    } else if (i < na + nb) {
        int j = i - na;
        float s = 0.f;
#pragma unroll
        for (int z = 0; z < SPLITK; ++z) s += pb[(size_t)z * nb + j];
        ob[j] = s;
    }
}

// ---------------- X[rows,64] @ Wr[48,64]^T -> out[rows,48] ----------------
__global__ void __launch_bounds__(256) projr_kernel(const float* __restrict__ X,
                                                    const float* __restrict__ Wr,
                                                    float* __restrict__ out, int rows) {
    int i = blockIdx.x * blockDim.x + threadIdx.x;
    if (i >= rows * RD) return;
    int n = i / RD, r = i % RD;
    const float* x = X + (size_t)n * BOTD;
    const float* w = Wr + (size_t)r * BOTD;
    float s = 0.f;
#pragma unroll
    for (int d = 0; d < BOTD; ++d) s += x[d] * w[d];
    out[i] = s;
}

// ---------------- router scores: rq[NTOK,48] @ rk[NSL,48]^T ----------------
__global__ void __launch_bounds__(256) scores_kernel(const float* __restrict__ rq,
                                                     const float* __restrict__ rk,
                                                     const float* __restrict__ log_rel,
                                                     float* __restrict__ scores) {
    constexpr int BT = 32, BSN = 128;
    __shared__ float s_rq[BT][RD + 1];
    __shared__ float s_rk[BSN][RD];
    const int t0 = blockIdx.y * BT, nb0 = blockIdx.x * BSN;
    const int tid = threadIdx.x;
    for (int i = tid; i < BT * RD; i += 256)
        s_rq[i / RD][i % RD] = rq[(size_t)(t0 + i / RD) * RD + i % RD];
    for (int i = tid; i < BSN * RD; i += 256)
        s_rk[i / RD][i % RD] = rk[(size_t)(nb0 + i / RD) * RD + i % RD];
    __syncthreads();
    const float sc = 0.14433756729740643f;  // 1/sqrt(48)
    const int tloc = tid & 31;
    const int nlo = (tid >> 5) * 16;
    for (int j = 0; j < 16; ++j) {
        int n = nlo + j;
        float s = 0.f;
#pragma unroll
        for (int r = 0; r < RD; ++r) s += s_rq[tloc][r] * s_rk[n][r];
        scores[(size_t)(t0 + tloc) * NSL + nb0 + n] = s * sc + log_rel[nb0 + n];
    }
}

// ---------------- per-token top-8 + attention + AV_d gather ----------------
__global__ void __launch_bounds__(256) router_topk_kernel(
    const float* __restrict__ scores, const float* __restrict__ query,
    const float* __restrict__ aux_keys, const float* __restrict__ log_rel,
    const float* __restrict__ AVd, __nv_bfloat16* __restrict__ tb) {
    const int t = blockIdx.x, tid = threadIdx.x;
    __shared__ __align__(16) float ssc[NSL];
    __shared__ float sq[BOTD];
    __shared__ float rv[256];
    __shared__ int ri[256];
    __shared__ int sel[KS];
    __shared__ float slog[KS];

    ((float4*)ssc)[tid] = ((const float4*)(scores + (size_t)t * NSL))[tid];
    if (tid < BOTD) sq[tid] = query[(size_t)t * BOTD + tid];
    __syncthreads();

    for (int k = 0; k < KS; ++k) {
        float bv = -INFINITY;
        int bi = 0;
#pragma unroll
        for (int j = 0; j < 4; ++j) {
            int idx = tid + j * 256;
            float v = ssc[idx];
            if (v > bv) { bv = v; bi = idx; }
        }
        rv[tid] = bv; ri[tid] = bi;
        __syncthreads();
        for (int s = 128; s > 0; s >>= 1) {
            if (tid < s) {
                float v2 = rv[tid + s]; int i2 = ri[tid + s];
                if (v2 > rv[tid] || (v2 == rv[tid] && i2 < ri[tid])) { rv[tid] = v2; ri[tid] = i2; }
            }
            __syncthreads();
        }
        if (tid == 0) { sel[k] = ri[0]; ssc[ri[0]] = -INFINITY; }
        __syncthreads();
    }

    // attention logits: 1 warp per selected slot
    const int w = tid >> 5, lane = tid & 31;
    {
        int idx = sel[w];
        const float* kr = aux_keys + (size_t)idx * BOTD;
        float s = sq[lane] * kr[lane] + sq[lane + 32] * kr[lane + 32];
#pragma unroll
        for (int o = 16; o > 0; o >>= 1) s += __shfl_xor_sync(0xffffffffu, s, o);
        if (lane == 0) slog[w] = s * 0.125f + log_rel[idx];
    }
    __syncthreads();

    // softmax over 8 (redundant across threads) + gather AV_d
    float m = slog[0];
#pragma unroll
    for (int k = 1; k < KS; ++k) m = fmaxf(m, slog[k]);
    float e[KS], sum = 0.f;
#pragma unroll
    for (int k = 0; k < KS; ++k) { e[k] = expf(slog[k] - m); sum += e[k]; }
    const float inv = 1.f / sum;
    float v = 0.f;
#pragma unroll
    for (int k = 0; k < KS; ++k) v += e[k] * inv * AVd[(size_t)sel[k] * VBD + tid];
    tb[(size_t)t * VBD + tid] = __float2bfloat16(v);
}

// ---------------- gate: global logvar mean -> per-token gate ----------------
__global__ void __launch_bounds__(1024) gate_kernel(const float* __restrict__ logvar,
                                                    const float* __restrict__ partial,
                                                    const float* __restrict__ bu2,
                                                    const float* __restrict__ gw1,
                                                    const float* __restrict__ gb,
                                                    float* __restrict__ gate) {
    __shared__ float red[1024];
    __shared__ float s_mean;
    const int tid = threadIdx.x;
    float s = 0.f;
    for (int i = tid; i < NTOK; i += 1024) s += logvar[i];
    red[tid] = s;
    __syncthreads();
    for (int st = 512; st > 0; st >>= 1) {
        if (tid < st) red[tid] += red[tid + st];
        __syncthreads();
    }
    if (tid == 0) s_mean = red[0] * (1.f / NTOK);
    __syncthreads();
    const float mean = s_mean;
    const float w1 = gw1[0], b = gb[0], b2 = bu2[0];
    for (int i = tid; i < NTOK; i += 1024) {
        float L = b2;
#pragma unroll
        for (int j = 0; j < 16; ++j) L += partial[j * NTOK + i];
        float nv = logvar[i] / (mean + 1e-6f);
        float u = fminf(fmaxf(nv * 0.5f + sigmoidf(L) * 2.5f, 0.f), 5.f);
        float un = fminf(fmaxf((u - 0.5f) * (1.f / 1.5f), 0.f), 1.f);
        float g = sigmoidf(w1 * un + b);
        gate[i] = (g < 0.05f) ? 0.f : g;
    }
}

// ---------------- launcher ----------------
extern "C" void kernel_launch(void* const* d_in, const int* in_sizes, int n_in,
                              void* d_out, int out_size) {
    const float* h        = (const float*)d_in[0];
    const float* Wq       = (const float*)d_in[1];
    const float* Wr       = (const float*)d_in[2];
    const float* aux_keys = (const float*)d_in[3];
    const float* aux_vals = (const float*)d_in[4];
    const float* Wvd      = (const float*)d_in[5];
    const float* Wvu      = (const float*)d_in[6];
    const float* Wu1      = (const float*)d_in[7];
    const float* bu1      = (const float*)d_in[8];
    const float* Wu2      = (const float*)d_in[9];
    const float* bu2      = (const float*)d_in[10];
    const float* gw1      = (const float*)d_in[11];
    const float* gb       = (const float*)d_in[12];
    const float* log_rel  = (const float*)d_in[13];
    float* out = (float*)d_out;

    __nv_bfloat16 *hb, *Wu1b, *Wqb, *avb, *Wvdb, *Wvub, *tb;
    float *query, *rq, *rk, *scores, *AVd, *AVd_part, *query_part, *partial, *logvar, *gate;
    cudaGetSymbolAddress((void**)&hb, g_hb);
    cudaGetSymbolAddress((void**)&Wu1b, g_Wu1b);
    cudaGetSymbolAddress((void**)&Wqb, g_Wqb);
    cudaGetSymbolAddress((void**)&avb, g_avb);
    cudaGetSymbolAddress((void**)&Wvdb, g_Wvdb);
    cudaGetSymbolAddress((void**)&Wvub, g_Wvub);
    cudaGetSymbolAddress((void**)&tb, g_tb);
    cudaGetSymbolAddress((void**)&query, g_query);
    cudaGetSymbolAddress((void**)&rq, g_rq);
    cudaGetSymbolAddress((void**)&rk, g_rk);
    cudaGetSymbolAddress((void**)&scores, g_scores);
    cudaGetSymbolAddress((void**)&AVd, g_AVd);
    cudaGetSymbolAddress((void**)&AVd_part, g_AVd_part);
    cudaGetSymbolAddress((void**)&query_part, g_query_part);
    cudaGetSymbolAddress((void**)&partial, g_partial);
    cudaGetSymbolAddress((void**)&logvar, g_logvar);
    cudaGetSymbolAddress((void**)&gate, g_gate);

    // dynamic smem sizes: 3-stage pipeline
    const int smem_128_128 = 3 * (128 + 128) * 40 * (int)sizeof(__nv_bfloat16);  // 61440
    const int smem_128_64  = 3 * (128 + 64) * 40 * (int)sizeof(__nv_bfloat16);   // 46080
    cudaFuncSetAttribute(gemm_tn<128, 128, 0>, cudaFuncAttributeMaxDynamicSharedMemorySize, smem_128_128);
    cudaFuncSetAttribute(gemm_tn<128, 128, 1>, cudaFuncAttributeMaxDynamicSharedMemorySize, smem_128_128);
    cudaFuncSetAttribute(gemm_tn<128, 128, 2>, cudaFuncAttributeMaxDynamicSharedMemorySize, smem_128_128);
    cudaFuncSetAttribute(gemm_tn<128, 64, 0>, cudaFuncAttributeMaxDynamicSharedMemorySize, smem_128_64);

    // h -> bf16 + per-token variance (fused)
    var_cvt_kernel<<<NTOK, 256>>>(h, hb, logvar);

    // all 5 weight converts in one launch (float4 granularity)
    {
        const int n0 = H4 * HIDD / 4, n1 = BOTD * HIDD / 4, n2 = NSL * HIDD / 4,
                  n3 = VBD * HIDD / 4, n4 = HIDD * VBD / 4;
        const int tot = n0 + n1 + n2 + n3 + n4;
        cvt_all_kernel<<<(tot + 255) / 256, 256>>>(
            Wu1, Wu1b, n0, Wq, Wqb, n1, aux_vals, avb, n2,
            Wvd, Wvdb, n3, Wvu, Wvub, n4);
    }

    // rk = aux_keys @ Wr^T
    projr_kernel<<<(NSL * RD + 255) / 256, 256>>>(aux_keys, Wr, rk, NSL);

    // AV_d partials = aux_values @ Wvd^T, split-K=8 -> grid 2x8x8 = 128 blocks
    gemm_tn<128, 128, 0><<<dim3(VBD / 128, NSL / 128, SPLITK), 256, smem_128_128>>>(
        avb, Wvdb, AVd_part, NSL, VBD, HIDD, nullptr, nullptr, nullptr);

    // query partials = h @ Wq^T, split-K=8 -> grid 1x32x8 = 256 blocks
    gemm_tn<128, 64, 0><<<dim3(1, NTOK / 128, SPLITK), 256, smem_128_64>>>(
        hb, Wqb, query_part, NTOK, BOTD, HIDD, nullptr, nullptr, nullptr);

    // reduce both split-K partials (fixed order -> deterministic)
    {
        const int na = NSL * VBD, nb = NTOK * BOTD;
        reduce_parts_kernel<<<(na + nb + 255) / 256, 256>>>(
            AVd_part, AVd, na, query_part, query, nb);
    }

    // partial = Wu2 . gelu(h @ Wu1^T + bu1)   (big GEMM, fused epilogue, deterministic)
    gemm_tn<128, 128, 1><<<dim3(H4 / 128, NTOK / 128, 1), 256, smem_128_128>>>(
        hb, Wu1b, nullptr, NTOK, H4, HIDD, bu1, Wu2, partial);

    // rq = query @ Wr^T
    projr_kernel<<<(NTOK * RD + 255) / 256, 256>>>(query, Wr, rq, NTOK);

    // router scores
    scores_kernel<<<dim3(NSL / 128, NTOK / 32), 256>>>(rq, rk, log_rel, scores);

    // top-8 + softmax + AV_d gather -> t (bf16)
    router_topk_kernel<<<NTOK, 256>>>(scores, query, aux_keys, log_rel, AVd, tb);

    // gate (needs global mean of logvar + learned)
    gate_kernel<<<1, 1024>>>(logvar, partial, bu2, gw1, gb, gate);

    // out = h + gate * (t @ Wvu^T)   (fused epilogue)
    gemm_tn<128, 128, 2><<<dim3(HIDD / 128, NTOK / 128, 1), 256, smem_128_128>>>(
        tb, Wvub, out, NTOK, HIDD, VBD, h, gate, nullptr);
}

// round 11
// speedup vs baseline: 1.0417x; 1.0417x over previous
#include <cuda_runtime.h>
#include <cuda_bf16.h>
#include <cstdint>
#include <math.h>

// ---------------- problem dims ----------------
#define NTOK 4096   // B*S = 2*2048
#define HIDD 4096
#define BOTD 64
#define RD   48
#define NSL  1024
#define KS   8
#define VBD  256
#define H4   1024   // HID/4
#define SPLITK 8

// ---------------- device scratch ----------------
__device__ __nv_bfloat16 g_hb[NTOK * HIDD];          // 32 MB
__device__ __nv_bfloat16 g_Wu1b[H4 * HIDD];          // 8 MB
__device__ __nv_bfloat16 g_Wqb[BOTD * HIDD];         // 0.5 MB
__device__ __nv_bfloat16 g_avb[NSL * HIDD];          // 8 MB
__device__ __nv_bfloat16 g_Wvdb[VBD * HIDD];         // 2 MB
__device__ __nv_bfloat16 g_Wvub[HIDD * VBD];         // 2 MB
__device__ float g_query[NTOK * BOTD];               // 1 MB
__device__ float g_rq[NTOK * RD];
__device__ float g_rk[NSL * RD];
__device__ float g_scores[NTOK * NSL];               // 16 MB
__device__ float g_AVd[NSL * VBD];                   // 1 MB
__device__ float g_AVd_part[SPLITK * NSL * VBD];     // 8 MB
__device__ float g_query_part[SPLITK * NTOK * BOTD]; // 8 MB
__device__ __nv_bfloat16 g_tb[NTOK * VBD];           // 2 MB
__device__ float g_partial[16 * NTOK];               // deterministic Wu2-dot partials
__device__ float g_logvar[NTOK];
__device__ float g_gate[NTOK];

// ---------------- small helpers ----------------
__device__ __forceinline__ uint32_t smem_u32(const void* p) {
    return (uint32_t)__cvta_generic_to_shared(p);
}
__device__ __forceinline__ void cp_async16(void* dst, const void* src) {
    asm volatile("cp.async.cg.shared.global [%0], [%1], 16;\n"
                 :: "r"(smem_u32(dst)), "l"(src));
}
__device__ __forceinline__ void cp_commit() { asm volatile("cp.async.commit_group;\n"); }
template <int N> __device__ __forceinline__ void cp_wait() {
    asm volatile("cp.async.wait_group %0;\n" :: "n"(N));
}
__device__ __forceinline__ float gelu_tanh(float x) {
    float x3 = x * x * x;
    return 0.5f * x * (1.0f + tanhf(0.7978845608028654f * (x + 0.044715f * x3)));
}
__device__ __forceinline__ float sigmoidf(float x) { return 1.0f / (1.0f + expf(-x)); }

// monotone key for float compare via unsigned
__device__ __forceinline__ uint32_t fkey(float v) {
    uint32_t u = __float_as_uint(v);
    return u ^ ((u >> 31) ? 0xFFFFFFFFu : 0x80000000u);
}

// ---------------- batched bf16 convert (5 weight tensors in one launch) ----------------
__global__ void __launch_bounds__(256) cvt_all_kernel(
    const float* __restrict__ s0, __nv_bfloat16* __restrict__ d0, int n0,
    const float* __restrict__ s1, __nv_bfloat16* __restrict__ d1, int n1,
    const float* __restrict__ s2, __nv_bfloat16* __restrict__ d2, int n2,
    const float* __restrict__ s3, __nv_bfloat16* __restrict__ d3, int n3,
    const float* __restrict__ s4, __nv_bfloat16* __restrict__ d4, int n4) {
    int i = blockIdx.x * blockDim.x + threadIdx.x;
    const float* src; __nv_bfloat16* dst; int local;
    if (i < n0)                       { src = s0; dst = d0; local = i; }
    else if (i < n0 + n1)             { src = s1; dst = d1; local = i - n0; }
    else if (i < n0 + n1 + n2)        { src = s2; dst = d2; local = i - n0 - n1; }
    else if (i < n0 + n1 + n2 + n3)   { src = s3; dst = d3; local = i - n0 - n1 - n2; }
    else if (i < n0 + n1 + n2 + n3 + n4) { src = s4; dst = d4; local = i - n0 - n1 - n2 - n3; }
    else return;
    float4 v = ((const float4*)src)[local];
    union { __nv_bfloat162 b2[2]; uint2 u; } p;
    p.b2[0] = __floats2bfloat162_rn(v.x, v.y);
    p.b2[1] = __floats2bfloat162_rn(v.z, v.w);
    ((uint2*)dst)[local] = p.u;
}

// ---------------- per-token variance + h->bf16 (fused) ----------------
__global__ void __launch_bounds__(256) var_cvt_kernel(const float* __restrict__ h,
                                                      __nv_bfloat16* __restrict__ hb,
                                                      float* __restrict__ logvar) {
    const int t = blockIdx.x, tid = threadIdx.x;
    const float4* row = (const float4*)(h + (size_t)t * HIDD);
    uint2* drow = (uint2*)(hb + (size_t)t * HIDD);
    float s = 0.f, ss = 0.f;
    for (int i = tid; i < HIDD / 4; i += 256) {
        float4 v = row[i];
        s += (v.x + v.y) + (v.z + v.w);
        ss += v.x * v.x + v.y * v.y + v.z * v.z + v.w * v.w;
        union { __nv_bfloat162 b2[2]; uint2 u; } p;
        p.b2[0] = __floats2bfloat162_rn(v.x, v.y);
        p.b2[1] = __floats2bfloat162_rn(v.z, v.w);
        drow[i] = p.u;
    }
    __shared__ float rs[256], rss[256];
    rs[tid] = s; rss[tid] = ss;
    __syncthreads();
    for (int st = 128; st > 0; st >>= 1) {
        if (tid < st) { rs[tid] += rs[tid + st]; rss[tid] += rss[tid + st]; }
        __syncthreads();
    }
    if (tid == 0) {
        float mean = rs[0] * (1.f / HIDD);
        float var = rss[0] * (1.f / HIDD) - mean * mean;
        logvar[t] = log1pf(var);
    }
}

// ---------------- bf16 TN GEMM, 3-stage cp.async pipeline (1 barrier/iter), split-K ----------------
// C[M,N] = A[M,K] * B[N,K]^T  over K-slice blockIdx.z (slice size Kd/gridDim.z)
// EPI 0: store C (f32) at slice offset blockIdx.z*M*N
// EPI 1: partial[(bx*2+wn)*NTOK+row] = sum_n Wu2[n]*gelu(acc+bu1[n]) (ep0=bu1, ep1=Wu2, ep2=partial)
// EPI 2: C[r,c] = ep0[r,c] + ep1[r]*acc                              (ep0=h, ep1=gate, C=out)
template <int BM, int BN, int EPI>
__global__ void __launch_bounds__(256)
gemm_tn(const __nv_bfloat16* __restrict__ A, const __nv_bfloat16* __restrict__ B,
        float* __restrict__ C, int M, int N, int Kd,
        const float* __restrict__ ep0, const float* __restrict__ ep1,
        float* __restrict__ ep2) {
    constexpr int BK = 32;
    constexpr int LDSW = BK + 8;           // 40 bf16 row pitch -> staggered banks
    constexpr int TM = BM / 4, TN = BN / 2;
    constexpr int MI = TM / 16, NI = TN / 8;

    extern __shared__ __align__(16) char dynsmem[];
    __nv_bfloat16* sAr = (__nv_bfloat16*)dynsmem;            // [3][BM][LDSW]
    __nv_bfloat16* sBr = sAr + 3 * BM * LDSW;                // [3][BN][LDSW]

    const int tid = threadIdx.x;
    const int warp = tid >> 5, lane = tid & 31;
    const int wm = warp & 3, wn = warp >> 2;   // 4x2 warp grid
    const int m0 = blockIdx.y * BM, n0 = blockIdx.x * BN;

    const int Kslice = Kd / gridDim.z;
    const int kbase = blockIdx.z * Kslice;
    const int KT = Kslice / BK;

    float acc[MI][NI][4];
#pragma unroll
    for (int i = 0; i < MI; ++i)
#pragma unroll
        for (int j = 0; j < NI; ++j) {
            acc[i][j][0] = acc[i][j][1] = acc[i][j][2] = acc[i][j][3] = 0.f;
        }

    auto load_tile = [&](int kt, int buf) {
        const int k0 = kbase + kt * BK;
        for (int c = tid; c < BM * 4; c += 256) {
            int r = c >> 2, kc = (c & 3) * 8;
            cp_async16(&sAr[(buf * BM + r) * LDSW + kc], A + (size_t)(m0 + r) * Kd + k0 + kc);
        }
        for (int c = tid; c < BN * 4; c += 256) {
            int r = c >> 2, kc = (c & 3) * 8;
            cp_async16(&sBr[(buf * BN + r) * LDSW + kc], B + (size_t)(n0 + r) * Kd + k0 + kc);
        }
    };

    load_tile(0, 0);
    cp_commit();
    load_tile(1, 1);
    cp_commit();

    for (int kt = 0; kt < KT; ++kt) {
        const int buf = kt % 3;
        if (kt + 1 < KT) cp_wait<1>(); else cp_wait<0>();
        __syncthreads();
        // all warps are past compute of kt-1 (buffer (kt+2)%3) -> safe to refill it now
        if (kt + 2 < KT) {
            load_tile(kt + 2, (kt + 2) % 3);
            cp_commit();
        }

#pragma unroll
        for (int kk = 0; kk < BK; kk += 16) {
            uint32_t af[MI][4];
#pragma unroll
            for (int mi = 0; mi < MI; ++mi) {
                uint32_t a = smem_u32(&sAr[(buf * BM + wm * TM + mi * 16 + (lane & 15)) * LDSW
                                           + kk + (lane >> 4) * 8]);
                asm volatile("ldmatrix.sync.aligned.m8n8.x4.shared.b16 {%0,%1,%2,%3}, [%4];"
                             : "=r"(af[mi][0]), "=r"(af[mi][1]),
                               "=r"(af[mi][2]), "=r"(af[mi][3]) : "r"(a));
            }
            uint32_t bfr[NI][2];
#pragma unroll
            for (int ni = 0; ni < NI; ni += 2) {
                // x4: {(ni,k0),(ni,k1),(ni+1,k0),(ni+1,k1)} via lane-group addressing
                uint32_t a = smem_u32(&sBr[(buf * BN + wn * TN + (ni + ((lane >> 4) & 1)) * 8
                                            + (lane & 7)) * LDSW
                                           + kk + ((lane >> 3) & 1) * 8]);
                asm volatile("ldmatrix.sync.aligned.m8n8.x4.shared.b16 {%0,%1,%2,%3}, [%4];"
                             : "=r"(bfr[ni][0]), "=r"(bfr[ni][1]),
                               "=r"(bfr[ni + 1][0]), "=r"(bfr[ni + 1][1]) : "r"(a));
            }
#pragma unroll
            for (int mi = 0; mi < MI; ++mi)
#pragma unroll
                for (int ni = 0; ni < NI; ++ni)
                    asm volatile(
                        "mma.sync.aligned.m16n8k16.row.col.f32.bf16.bf16.f32 "
                        "{%0,%1,%2,%3}, {%4,%5,%6,%7}, {%8,%9}, {%0,%1,%2,%3};"
                        : "+f"(acc[mi][ni][0]), "+f"(acc[mi][ni][1]),
                          "+f"(acc[mi][ni][2]), "+f"(acc[mi][ni][3])
                        : "r"(af[mi][0]), "r"(af[mi][1]), "r"(af[mi][2]), "r"(af[mi][3]),
                          "r"(bfr[ni][0]), "r"(bfr[ni][1]));
        }
    }

    const int row0 = m0 + wm * TM;
    if (EPI == 0) {
        float* Cs = C + (size_t)blockIdx.z * M * N;
#pragma unroll
        for (int mi = 0; mi < MI; ++mi) {
            int r = row0 + mi * 16 + (lane >> 2);
#pragma unroll
            for (int ni = 0; ni < NI; ++ni) {
                int c = n0 + wn * TN + ni * 8 + (lane & 3) * 2;
                *(float2*)&Cs[(size_t)r * N + c] = make_float2(acc[mi][ni][0], acc[mi][ni][1]);
                *(float2*)&Cs[(size_t)(r + 8) * N + c] = make_float2(acc[mi][ni][2], acc[mi][ni][3]);
            }
        }
    } else if (EPI == 1) {
        // one writer per (blockIdx.x, wn, row) -> deterministic
        float* pout = ep2 + (size_t)(blockIdx.x * 2 + wn) * NTOK;
#pragma unroll
        for (int mi = 0; mi < MI; ++mi) {
            float p0 = 0.f, p1 = 0.f;
#pragma unroll
            for (int ni = 0; ni < NI; ++ni) {
                int c = n0 + wn * TN + ni * 8 + (lane & 3) * 2;
                float b0 = ep0[c], b1 = ep0[c + 1];
                float w0 = ep1[c], w1 = ep1[c + 1];
                p0 += gelu_tanh(acc[mi][ni][0] + b0) * w0 + gelu_tanh(acc[mi][ni][1] + b1) * w1;
                p1 += gelu_tanh(acc[mi][ni][2] + b0) * w0 + gelu_tanh(acc[mi][ni][3] + b1) * w1;
            }
            p0 += __shfl_xor_sync(0xffffffffu, p0, 1);
            p0 += __shfl_xor_sync(0xffffffffu, p0, 2);
            p1 += __shfl_xor_sync(0xffffffffu, p1, 1);
            p1 += __shfl_xor_sync(0xffffffffu, p1, 2);
            if ((lane & 3) == 0) {
                pout[row0 + mi * 16 + (lane >> 2)] = p0;
                pout[row0 + mi * 16 + (lane >> 2) + 8] = p1;
            }
        }
    } else {  // EPI == 2
#pragma unroll
        for (int mi = 0; mi < MI; ++mi) {
            int r = row0 + mi * 16 + (lane >> 2);
            float g0 = ep1[r], g1 = ep1[r + 8];
#pragma unroll
            for (int ni = 0; ni < NI; ++ni) {
                int c = n0 + wn * TN + ni * 8 + (lane & 3) * 2;
                size_t i0 = (size_t)r * N + c;
                float2 h0 = *(const float2*)&ep0[i0];
                *(float2*)&C[i0] = make_float2(h0.x + g0 * acc[mi][ni][0],
                                               h0.y + g0 * acc[mi][ni][1]);
                size_t i1 = (size_t)(r + 8) * N + c;
                float2 h1 = *(const float2*)&ep0[i1];
                *(float2*)&C[i1] = make_float2(h1.x + g1 * acc[mi][ni][2],
                                               h1.y + g1 * acc[mi][ni][3]);
            }
        }
    }
}

// ---------------- split-K reduction for AVd and query (fixed order, deterministic) ----------------
__global__ void __launch_bounds__(256) reduce_parts_kernel(
    const float* __restrict__ pa, float* __restrict__ oa, int na,
    const float* __restrict__ pb, float* __restrict__ ob, int nb) {
    int i = blockIdx.x * blockDim.x + threadIdx.x;
    if (i < na) {
        float s = 0.f;
#pragma unroll
        for (int z = 0; z < SPLITK; ++z) s += pa[(size_t)z * na + i];
        oa[i] = s;
    } else if (i < na + nb) {
        int j = i - na;
        float s = 0.f;
#pragma unroll
        for (int z = 0; z < SPLITK; ++z) s += pb[(size_t)z * nb + j];
        ob[j] = s;
    }
}

// ---------------- X[rows,64] @ Wr[48,64]^T -> out[rows,48] ----------------
__global__ void __launch_bounds__(256) projr_kernel(const float* __restrict__ X,
                                                    const float* __restrict__ Wr,
                                                    float* __restrict__ out, int rows) {
    int i = blockIdx.x * blockDim.x + threadIdx.x;
    if (i >= rows * RD) return;
    int n = i / RD, r = i % RD;
    const float* x = X + (size_t)n * BOTD;
    const float* w = Wr + (size_t)r * BOTD;
    float s = 0.f;
#pragma unroll
    for (int d = 0; d < BOTD; ++d) s += x[d] * w[d];
    out[i] = s;
}

// ---------------- router scores: rq[NTOK,48] @ rk[NSL,48]^T ----------------
__global__ void __launch_bounds__(256) scores_kernel(const float* __restrict__ rq,
                                                     const float* __restrict__ rk,
                                                     const float* __restrict__ log_rel,
                                                     float* __restrict__ scores) {
    constexpr int BT = 32, BSN = 128;
    __shared__ float s_rq[BT][RD + 1];
    __shared__ float s_rk[BSN][RD];
    const int t0 = blockIdx.y * BT, nb0 = blockIdx.x * BSN;
    const int tid = threadIdx.x;
    for (int i = tid; i < BT * RD; i += 256)
        s_rq[i / RD][i % RD] = rq[(size_t)(t0 + i / RD) * RD + i % RD];
    for (int i = tid; i < BSN * RD; i += 256)
        s_rk[i / RD][i % RD] = rk[(size_t)(nb0 + i / RD) * RD + i % RD];
    __syncthreads();
    const float sc = 0.14433756729740643f;  // 1/sqrt(48)
    const int tloc = tid & 31;
    const int nlo = (tid >> 5) * 16;
    for (int j = 0; j < 16; ++j) {
        int n = nlo + j;
        float s = 0.f;
#pragma unroll
        for (int r = 0; r < RD; ++r) s += s_rq[tloc][r] * s_rk[n][r];
        scores[(size_t)(t0 + tloc) * NSL + nb0 + n] = s * sc + log_rel[nb0 + n];
    }
}

// ---------------- per-token top-8 + attention + AV_d gather (shuffle reduce) ----------------
__global__ void __launch_bounds__(256) router_topk_kernel(
    const float* __restrict__ scores, const float* __restrict__ query,
    const float* __restrict__ aux_keys, const float* __restrict__ log_rel,
    const float* __restrict__ AVd, __nv_bfloat16* __restrict__ tb) {
    const int t = blockIdx.x, tid = threadIdx.x;
    const int w = tid >> 5, lane = tid & 31;
    __shared__ __align__(16) float ssc[NSL];
    __shared__ float sq[BOTD];
    __shared__ unsigned long long wred[8];
    __shared__ int sel[KS];
    __shared__ float slog[KS];

    ((float4*)ssc)[tid] = ((const float4*)(scores + (size_t)t * NSL))[tid];
    if (tid < BOTD) sq[tid] = query[(size_t)t * BOTD + tid];
    __syncthreads();

    for (int k = 0; k < KS; ++k) {
        unsigned long long best = 0ull;
#pragma unroll
        for (int j = 0; j < 4; ++j) {
            int idx = tid + j * 256;
            unsigned long long p = ((unsigned long long)fkey(ssc[idx]) << 32)
                                   | (unsigned)(NSL - 1 - idx);
            best = (p > best) ? p : best;
        }
#pragma unroll
        for (int o = 16; o > 0; o >>= 1) {
            unsigned long long q = __shfl_xor_sync(0xffffffffu, best, o);
            best = (q > best) ? q : best;
        }
        if (lane == 0) wred[w] = best;
        __syncthreads();
        if (tid < 8) {
            unsigned long long b = wred[tid];
#pragma unroll
            for (int o = 4; o > 0; o >>= 1) {
                unsigned long long q = __shfl_xor_sync(0xffu, b, o);
                b = (q > b) ? q : b;
            }
            if (tid == 0) {
                int idx = NSL - 1 - (int)(b & 0xFFFFFFFFu);
                sel[k] = idx;
                ssc[idx] = -INFINITY;
            }
        }
        __syncthreads();
    }

    // attention logits: 1 warp per selected slot
    {
        int idx = sel[w];
        const float* kr = aux_keys + (size_t)idx * BOTD;
        float s = sq[lane] * kr[lane] + sq[lane + 32] * kr[lane + 32];
#pragma unroll
        for (int o = 16; o > 0; o >>= 1) s += __shfl_xor_sync(0xffffffffu, s, o);
        if (lane == 0) slog[w] = s * 0.125f + log_rel[idx];
    }
    __syncthreads();

    // softmax over 8 (redundant across threads) + gather AV_d
    float m = slog[0];
#pragma unroll
    for (int k = 1; k < KS; ++k) m = fmaxf(m, slog[k]);
    float e[KS], sum = 0.f;
#pragma unroll
    for (int k = 0; k < KS; ++k) { e[k] = expf(slog[k] - m); sum += e[k]; }
    const float inv = 1.f / sum;
    float v = 0.f;
#pragma unroll
    for (int k = 0; k < KS; ++k) v += e[k] * inv * AVd[(size_t)sel[k] * VBD + tid];
    tb[(size_t)t * VBD + tid] = __float2bfloat16(v);
}

// ---------------- gate: global logvar mean -> per-token gate ----------------
__global__ void __launch_bounds__(1024) gate_kernel(const float* __restrict__ logvar,
                                                    const float* __restrict__ partial,
                                                    const float* __restrict__ bu2,
                                                    const float* __restrict__ gw1,
                                                    const float* __restrict__ gb,
                                                    float* __restrict__ gate) {
    __shared__ float red[1024];
    __shared__ float s_mean;
    const int tid = threadIdx.x;
    float s = 0.f;
    for (int i = tid; i < NTOK; i += 1024) s += logvar[i];
    red[tid] = s;
    __syncthreads();
    for (int st = 512; st > 0; st >>= 1) {
        if (tid < st) red[tid] += red[tid + st];
        __syncthreads();
    }
    if (tid == 0) s_mean = red[0] * (1.f / NTOK);
    __syncthreads();
    const float mean = s_mean;
    const float w1 = gw1[0], b = gb[0], b2 = bu2[0];
    for (int i = tid; i < NTOK; i += 1024) {
        float L = b2;
#pragma unroll
        for (int j = 0; j < 16; ++j) L += partial[j * NTOK + i];
        float nv = logvar[i] / (mean + 1e-6f);
        float u = fminf(fmaxf(nv * 0.5f + sigmoidf(L) * 2.5f, 0.f), 5.f);
        float un = fminf(fmaxf((u - 0.5f) * (1.f / 1.5f), 0.f), 1.f);
        float g = sigmoidf(w1 * un + b);
        gate[i] = (g < 0.05f) ? 0.f : g;
    }
}

// ---------------- launcher ----------------
extern "C" void kernel_launch(void* const* d_in, const int* in_sizes, int n_in,
                              void* d_out, int out_size) {
    const float* h        = (const float*)d_in[0];
    const float* Wq       = (const float*)d_in[1];
    const float* Wr       = (const float*)d_in[2];
    const float* aux_keys = (const float*)d_in[3];
    const float* aux_vals = (const float*)d_in[4];
    const float* Wvd      = (const float*)d_in[5];
    const float* Wvu      = (const float*)d_in[6];
    const float* Wu1      = (const float*)d_in[7];
    const float* bu1      = (const float*)d_in[8];
    const float* Wu2      = (const float*)d_in[9];
    const float* bu2      = (const float*)d_in[10];
    const float* gw1      = (const float*)d_in[11];
    const float* gb       = (const float*)d_in[12];
    const float* log_rel  = (const float*)d_in[13];
    float* out = (float*)d_out;

    __nv_bfloat16 *hb, *Wu1b, *Wqb, *avb, *Wvdb, *Wvub, *tb;
    float *query, *rq, *rk, *scores, *AVd, *AVd_part, *query_part, *partial, *logvar, *gate;
    cudaGetSymbolAddress((void**)&hb, g_hb);
    cudaGetSymbolAddress((void**)&Wu1b, g_Wu1b);
    cudaGetSymbolAddress((void**)&Wqb, g_Wqb);
    cudaGetSymbolAddress((void**)&avb, g_avb);
    cudaGetSymbolAddress((void**)&Wvdb, g_Wvdb);
    cudaGetSymbolAddress((void**)&Wvub, g_Wvub);
    cudaGetSymbolAddress((void**)&tb, g_tb);
    cudaGetSymbolAddress((void**)&query, g_query);
    cudaGetSymbolAddress((void**)&rq, g_rq);
    cudaGetSymbolAddress((void**)&rk, g_rk);
    cudaGetSymbolAddress((void**)&scores, g_scores);
    cudaGetSymbolAddress((void**)&AVd, g_AVd);
    cudaGetSymbolAddress((void**)&AVd_part, g_AVd_part);
    cudaGetSymbolAddress((void**)&query_part, g_query_part);
    cudaGetSymbolAddress((void**)&partial, g_partial);
    cudaGetSymbolAddress((void**)&logvar, g_logvar);
    cudaGetSymbolAddress((void**)&gate, g_gate);

    // dynamic smem sizes: 3-stage pipeline
    const int smem_128_128 = 3 * (128 + 128) * 40 * (int)sizeof(__nv_bfloat16);  // 61440
    const int smem_128_64  = 3 * (128 + 64) * 40 * (int)sizeof(__nv_bfloat16);   // 46080
    cudaFuncSetAttribute(gemm_tn<128, 128, 0>, cudaFuncAttributeMaxDynamicSharedMemorySize, smem_128_128);
    cudaFuncSetAttribute(gemm_tn<128, 128, 1>, cudaFuncAttributeMaxDynamicSharedMemorySize, smem_128_128);
    cudaFuncSetAttribute(gemm_tn<128, 128, 2>, cudaFuncAttributeMaxDynamicSharedMemorySize, smem_128_128);
    cudaFuncSetAttribute(gemm_tn<128, 64, 0>, cudaFuncAttributeMaxDynamicSharedMemorySize, smem_128_64);

    // h -> bf16 + per-token variance (fused)
    var_cvt_kernel<<<NTOK, 256>>>(h, hb, logvar);

    // all 5 weight converts in one launch (float4 granularity)
    {
        const int n0 = H4 * HIDD / 4, n1 = BOTD * HIDD / 4, n2 = NSL * HIDD / 4,
                  n3 = VBD * HIDD / 4, n4 = HIDD * VBD / 4;
        const int tot = n0 + n1 + n2 + n3 + n4;
        cvt_all_kernel<<<(tot + 255) / 256, 256>>>(
            Wu1, Wu1b, n0, Wq, Wqb, n1, aux_vals, avb, n2,
            Wvd, Wvdb, n3, Wvu, Wvub, n4);
    }

    // rk = aux_keys @ Wr^T
    projr_kernel<<<(NSL * RD + 255) / 256, 256>>>(aux_keys, Wr, rk, NSL);

    // AV_d partials = aux_values @ Wvd^T, split-K=8 -> grid 2x8x8 = 128 blocks
    gemm_tn<128, 128, 0><<<dim3(VBD / 128, NSL / 128, SPLITK), 256, smem_128_128>>>(
        avb, Wvdb, AVd_part, NSL, VBD, HIDD, nullptr, nullptr, nullptr);

    // query partials = h @ Wq^T, split-K=8 -> grid 1x32x8 = 256 blocks
    gemm_tn<128, 64, 0><<<dim3(1, NTOK / 128, SPLITK), 256, smem_128_64>>>(
        hb, Wqb, query_part, NTOK, BOTD, HIDD, nullptr, nullptr, nullptr);

    // reduce both split-K partials (fixed order -> deterministic)
    {
        const int na = NSL * VBD, nb = NTOK * BOTD;
        reduce_parts_kernel<<<(na + nb + 255) / 256, 256>>>(
            AVd_part, AVd, na, query_part, query, nb);
    }

    // partial = Wu2 . gelu(h @ Wu1^T + bu1)   (big GEMM, fused epilogue, deterministic)
    gemm_tn<128, 128, 1><<<dim3(H4 / 128, NTOK / 128, 1), 256, smem_128_128>>>(
        hb, Wu1b, nullptr, NTOK, H4, HIDD, bu1, Wu2, partial);

    // rq = query @ Wr^T
    projr_kernel<<<(NTOK * RD + 255) / 256, 256>>>(query, Wr, rq, NTOK);

    // router scores
    scores_kernel<<<dim3(NSL / 128, NTOK / 32), 256>>>(rq, rk, log_rel, scores);

    // top-8 + softmax + AV_d gather -> t (bf16)
    router_topk_kernel<<<NTOK, 256>>>(scores, query, aux_keys, log_rel, AVd, tb);

    // gate (needs global mean of logvar + learned)
    gate_kernel<<<1, 1024>>>(logvar, partial, bu2, gw1, gb, gate);

    // out = h + gate * (t @ Wvu^T)   (fused epilogue)
    gemm_tn<128, 128, 2><<<dim3(HIDD / 128, NTOK / 128, 1), 256, smem_128_128>>>(
        tb, Wvub, out, NTOK, HIDD, VBD, h, gate, nullptr);
}

// round 12
// speedup vs baseline: 1.0599x; 1.0175x over previous
#include <cuda_runtime.h>
#include <cuda_bf16.h>
#include <cstdint>
#include <math.h>

// ---------------- problem dims ----------------
#define NTOK 4096   // B*S = 2*2048
#define HIDD 4096
#define BOTD 64
#define RD   48
#define NSL  1024
#define KS   8
#define VBD  256
#define H4   1024   // HID/4
#define SPLITK 16

// ---------------- device scratch ----------------
__device__ __nv_bfloat16 g_hb[NTOK * HIDD];          // 32 MB
__device__ __nv_bfloat16 g_Wu1b[H4 * HIDD];          // 8 MB
__device__ __nv_bfloat16 g_Wqb[BOTD * HIDD];         // 0.5 MB
__device__ __nv_bfloat16 g_avb[NSL * HIDD];          // 8 MB
__device__ __nv_bfloat16 g_Wvdb[VBD * HIDD];         // 2 MB
__device__ __nv_bfloat16 g_Wvub[HIDD * VBD];         // 2 MB
__device__ float g_query[NTOK * BOTD];               // 1 MB
__device__ float g_rq[NTOK * RD];
__device__ float g_rk[NSL * RD];
__device__ float g_scores[NTOK * NSL];               // 16 MB
__device__ float g_AVd[NSL * VBD];                   // 1 MB
__device__ float g_AVd_part[SPLITK * NSL * VBD];     // 16 MB
__device__ float g_query_part[SPLITK * NTOK * BOTD]; // 16 MB
__device__ __nv_bfloat16 g_tb[NTOK * VBD];           // 2 MB
__device__ float g_partial[16 * NTOK];               // deterministic Wu2-dot partials
__device__ float g_logvar[NTOK];
__device__ float g_gate[NTOK];

// ---------------- small helpers ----------------
__device__ __forceinline__ uint32_t smem_u32(const void* p) {
    return (uint32_t)__cvta_generic_to_shared(p);
}
__device__ __forceinline__ void cp_async16(void* dst, const void* src) {
    asm volatile("cp.async.cg.shared.global [%0], [%1], 16;\n"
                 :: "r"(smem_u32(dst)), "l"(src));
}
__device__ __forceinline__ void cp_commit() { asm volatile("cp.async.commit_group;\n"); }
template <int N> __device__ __forceinline__ void cp_wait() {
    asm volatile("cp.async.wait_group %0;\n" :: "n"(N));
}
__device__ __forceinline__ float gelu_tanh(float x) {
    float x3 = x * x * x;
    return 0.5f * x * (1.0f + tanhf(0.7978845608028654f * (x + 0.044715f * x3)));
}
__device__ __forceinline__ float sigmoidf(float x) { return 1.0f / (1.0f + expf(-x)); }

// monotone key for float compare via unsigned
__device__ __forceinline__ uint32_t fkey(float v) {
    uint32_t u = __float_as_uint(v);
    return u ^ ((u >> 31) ? 0xFFFFFFFFu : 0x80000000u);
}

// ---------------- batched bf16 convert (5 weight tensors in one launch) ----------------
__global__ void __launch_bounds__(256) cvt_all_kernel(
    const float* __restrict__ s0, __nv_bfloat16* __restrict__ d0, int n0,
    const float* __restrict__ s1, __nv_bfloat16* __restrict__ d1, int n1,
    const float* __restrict__ s2, __nv_bfloat16* __restrict__ d2, int n2,
    const float* __restrict__ s3, __nv_bfloat16* __restrict__ d3, int n3,
    const float* __restrict__ s4, __nv_bfloat16* __restrict__ d4, int n4) {
    int i = blockIdx.x * blockDim.x + threadIdx.x;
    const float* src; __nv_bfloat16* dst; int local;
    if (i < n0)                       { src = s0; dst = d0; local = i; }
    else if (i < n0 + n1)             { src = s1; dst = d1; local = i - n0; }
    else if (i < n0 + n1 + n2)        { src = s2; dst = d2; local = i - n0 - n1; }
    else if (i < n0 + n1 + n2 + n3)   { src = s3; dst = d3; local = i - n0 - n1 - n2; }
    else if (i < n0 + n1 + n2 + n3 + n4) { src = s4; dst = d4; local = i - n0 - n1 - n2 - n3; }
    else return;
    float4 v = ((const float4*)src)[local];
    union { __nv_bfloat162 b2[2]; uint2 u; } p;
    p.b2[0] = __floats2bfloat162_rn(v.x, v.y);
    p.b2[1] = __floats2bfloat162_rn(v.z, v.w);
    ((uint2*)dst)[local] = p.u;
}

// ---------------- per-token variance + h->bf16 (fused) ----------------
__global__ void __launch_bounds__(256) var_cvt_kernel(const float* __restrict__ h,
                                                      __nv_bfloat16* __restrict__ hb,
                                                      float* __restrict__ logvar) {
    const int t = blockIdx.x, tid = threadIdx.x;
    const float4* row = (const float4*)(h + (size_t)t * HIDD);
    uint2* drow = (uint2*)(hb + (size_t)t * HIDD);
    float s = 0.f, ss = 0.f;
    for (int i = tid; i < HIDD / 4; i += 256) {
        float4 v = row[i];
        s += (v.x + v.y) + (v.z + v.w);
        ss += v.x * v.x + v.y * v.y + v.z * v.z + v.w * v.w;
        union { __nv_bfloat162 b2[2]; uint2 u; } p;
        p.b2[0] = __floats2bfloat162_rn(v.x, v.y);
        p.b2[1] = __floats2bfloat162_rn(v.z, v.w);
        drow[i] = p.u;
    }
    __shared__ float rs[256], rss[256];
    rs[tid] = s; rss[tid] = ss;
    __syncthreads();
    for (int st = 128; st > 0; st >>= 1) {
        if (tid < st) { rs[tid] += rs[tid + st]; rss[tid] += rss[tid + st]; }
        __syncthreads();
    }
    if (tid == 0) {
        float mean = rs[0] * (1.f / HIDD);
        float var = rss[0] * (1.f / HIDD) - mean * mean;
        logvar[t] = log1pf(var);
    }
}

// ---------------- bf16 TN GEMM, 3-stage cp.async + reg-double-buffered frags ----------------
// C[M,N] = A[M,K] * B[N,K]^T  over K-slice blockIdx.z (slice size Kd/gridDim.z)
// EPI 0: store C (f32) at slice offset blockIdx.z*M*N
// EPI 1: partial[(bx*2+wn)*NTOK+row] = sum_n Wu2[n]*gelu(acc+bu1[n]) (ep0=bu1, ep1=Wu2, ep2=partial)
// EPI 2: C[r,c] = ep0[r,c] + ep1[r]*acc                              (ep0=h, ep1=gate, C=out)
template <int BM, int BN, int EPI>
__global__ void __launch_bounds__(256, 2)
gemm_tn(const __nv_bfloat16* __restrict__ A, const __nv_bfloat16* __restrict__ B,
        float* __restrict__ C, int M, int N, int Kd,
        const float* __restrict__ ep0, const float* __restrict__ ep1,
        float* __restrict__ ep2) {
    constexpr int BK = 32;
    constexpr int LDSW = BK + 8;           // 40 bf16 row pitch -> staggered banks
    constexpr int TM = BM / 4, TN = BN / 2;
    constexpr int MI = TM / 16, NI = TN / 8;

    extern __shared__ __align__(16) char dynsmem[];
    __nv_bfloat16* sAr = (__nv_bfloat16*)dynsmem;            // [3][BM][LDSW]
    __nv_bfloat16* sBr = sAr + 3 * BM * LDSW;                // [3][BN][LDSW]

    const int tid = threadIdx.x;
    const int warp = tid >> 5, lane = tid & 31;
    const int wm = warp & 3, wn = warp >> 2;   // 4x2 warp grid
    const int m0 = blockIdx.y * BM, n0 = blockIdx.x * BN;

    const int Kslice = Kd / gridDim.z;
    const int kbase = blockIdx.z * Kslice;
    const int KT = Kslice / BK;

    float acc[MI][NI][4];
#pragma unroll
    for (int i = 0; i < MI; ++i)
#pragma unroll
        for (int j = 0; j < NI; ++j) {
            acc[i][j][0] = acc[i][j][1] = acc[i][j][2] = acc[i][j][3] = 0.f;
        }

    auto load_tile = [&](int kt, int buf) {
        const int k0 = kbase + kt * BK;
        for (int c = tid; c < BM * 4; c += 256) {
            int r = c >> 2, kc = (c & 3) * 8;
            cp_async16(&sAr[(buf * BM + r) * LDSW + kc], A + (size_t)(m0 + r) * Kd + k0 + kc);
        }
        for (int c = tid; c < BN * 4; c += 256) {
            int r = c >> 2, kc = (c & 3) * 8;
            cp_async16(&sBr[(buf * BN + r) * LDSW + kc], B + (size_t)(n0 + r) * Kd + k0 + kc);
        }
    };

    // fragment double buffers
    uint32_t af[2][MI][4];
    uint32_t bfr[2][NI][2];

    auto load_frags = [&](int buf, int kk, int sel) {
#pragma unroll
        for (int mi = 0; mi < MI; ++mi) {
            uint32_t a = smem_u32(&sAr[(buf * BM + wm * TM + mi * 16 + (lane & 15)) * LDSW
                                       + kk + (lane >> 4) * 8]);
            asm volatile("ldmatrix.sync.aligned.m8n8.x4.shared.b16 {%0,%1,%2,%3}, [%4];"
                         : "=r"(af[sel][mi][0]), "=r"(af[sel][mi][1]),
                           "=r"(af[sel][mi][2]), "=r"(af[sel][mi][3]) : "r"(a));
        }
#pragma unroll
        for (int ni = 0; ni < NI; ni += 2) {
            uint32_t a = smem_u32(&sBr[(buf * BN + wn * TN + (ni + ((lane >> 4) & 1)) * 8
                                        + (lane & 7)) * LDSW
                                       + kk + ((lane >> 3) & 1) * 8]);
            asm volatile("ldmatrix.sync.aligned.m8n8.x4.shared.b16 {%0,%1,%2,%3}, [%4];"
                         : "=r"(bfr[sel][ni][0]), "=r"(bfr[sel][ni][1]),
                           "=r"(bfr[sel][ni + 1][0]), "=r"(bfr[sel][ni + 1][1]) : "r"(a));
        }
    };

    load_tile(0, 0);
    cp_commit();
    load_tile(1, 1);
    cp_commit();

    for (int kt = 0; kt < KT; ++kt) {
        const int buf = kt % 3;
        if (kt + 1 < KT) cp_wait<1>(); else cp_wait<0>();
        __syncthreads();
        // all warps are past compute of kt-1 (buffer (kt+2)%3) -> safe to refill it now
        if (kt + 2 < KT) {
            load_tile(kt + 2, (kt + 2) % 3);
            cp_commit();
        }

        load_frags(buf, 0, 0);
#pragma unroll
        for (int s = 0; s < BK / 16; ++s) {
            const int cur = s & 1;
            if (s + 1 < BK / 16) load_frags(buf, (s + 1) * 16, cur ^ 1);
#pragma unroll
            for (int mi = 0; mi < MI; ++mi)
#pragma unroll
                for (int ni = 0; ni < NI; ++ni)
                    asm volatile(
                        "mma.sync.aligned.m16n8k16.row.col.f32.bf16.bf16.f32 "
                        "{%0,%1,%2,%3}, {%4,%5,%6,%7}, {%8,%9}, {%0,%1,%2,%3};"
                        : "+f"(acc[mi][ni][0]), "+f"(acc[mi][ni][1]),
                          "+f"(acc[mi][ni][2]), "+f"(acc[mi][ni][3])
                        : "r"(af[cur][mi][0]), "r"(af[cur][mi][1]),
                          "r"(af[cur][mi][2]), "r"(af[cur][mi][3]),
                          "r"(bfr[cur][ni][0]), "r"(bfr[cur][ni][1]));
        }
    }

    const int row0 = m0 + wm * TM;
    if (EPI == 0) {
        float* Cs = C + (size_t)blockIdx.z * M * N;
#pragma unroll
        for (int mi = 0; mi < MI; ++mi) {
            int r = row0 + mi * 16 + (lane >> 2);
#pragma unroll
            for (int ni = 0; ni < NI; ++ni) {
                int c = n0 + wn * TN + ni * 8 + (lane & 3) * 2;
                *(float2*)&Cs[(size_t)r * N + c] = make_float2(acc[mi][ni][0], acc[mi][ni][1]);
                *(float2*)&Cs[(size_t)(r + 8) * N + c] = make_float2(acc[mi][ni][2], acc[mi][ni][3]);
            }
        }
    } else if (EPI == 1) {
        // one writer per (blockIdx.x, wn, row) -> deterministic
        float* pout = ep2 + (size_t)(blockIdx.x * 2 + wn) * NTOK;
#pragma unroll
        for (int mi = 0; mi < MI; ++mi) {
            float p0 = 0.f, p1 = 0.f;
#pragma unroll
            for (int ni = 0; ni < NI; ++ni) {
                int c = n0 + wn * TN + ni * 8 + (lane & 3) * 2;
                float b0 = ep0[c], b1 = ep0[c + 1];
                float w0 = ep1[c], w1 = ep1[c + 1];
                p0 += gelu_tanh(acc[mi][ni][0] + b0) * w0 + gelu_tanh(acc[mi][ni][1] + b1) * w1;
                p1 += gelu_tanh(acc[mi][ni][2] + b0) * w0 + gelu_tanh(acc[mi][ni][3] + b1) * w1;
            }
            p0 += __shfl_xor_sync(0xffffffffu, p0, 1);
            p0 += __shfl_xor_sync(0xffffffffu, p0, 2);
            p1 += __shfl_xor_sync(0xffffffffu, p1, 1);
            p1 += __shfl_xor_sync(0xffffffffu, p1, 2);
            if ((lane & 3) == 0) {
                pout[row0 + mi * 16 + (lane >> 2)] = p0;
                pout[row0 + mi * 16 + (lane >> 2) + 8] = p1;
            }
        }
    } else {  // EPI == 2
#pragma unroll
        for (int mi = 0; mi < MI; ++mi) {
            int r = row0 + mi * 16 + (lane >> 2);
            float g0 = ep1[r], g1 = ep1[r + 8];
#pragma unroll
            for (int ni = 0; ni < NI; ++ni) {
                int c = n0 + wn * TN + ni * 8 + (lane & 3) * 2;
                size_t i0 = (size_t)r * N + c;
                float2 h0 = *(const float2*)&ep0[i0];
                *(float2*)&C[i0] = make_float2(h0.x + g0 * acc[mi][ni][0],
                                               h0.y + g0 * acc[mi][ni][1]);
                size_t i1 = (size_t)(r + 8) * N + c;
                float2 h1 = *(const float2*)&ep0[i1];
                *(float2*)&C[i1] = make_float2(h1.x + g1 * acc[mi][ni][2],
                                               h1.y + g1 * acc[mi][ni][3]);
            }
        }
    }
}

// ---------------- split-K reduction for AVd and query (fixed order, deterministic) ----------------
__global__ void __launch_bounds__(256) reduce_parts_kernel(
    const float* __restrict__ pa, float* __restrict__ oa, int na,
    const float* __restrict__ pb, float* __restrict__ ob, int nb) {
    int i = blockIdx.x * blockDim.x + threadIdx.x;
    if (i < na) {
        float s = 0.f;
#pragma unroll
        for (int z = 0; z < SPLITK; ++z) s += pa[(size_t)z * na + i];
        oa[i] = s;
    } else if (i < na + nb) {
        int j = i - na;
        float s = 0.f;
#pragma unroll
        for (int z = 0; z < SPLITK; ++z) s += pb[(size_t)z * nb + j];
        ob[j] = s;
    }
}

// ---------------- X[rows,64] @ Wr[48,64]^T -> out[rows,48] ----------------
__global__ void __launch_bounds__(256) projr_kernel(const float* __restrict__ X,
                                                    const float* __restrict__ Wr,
                                                    float* __restrict__ out, int rows) {
    int i = blockIdx.x * blockDim.x + threadIdx.x;
    if (i >= rows * RD) return;
    int n = i / RD, r = i % RD;
    const float* x = X + (size_t)n * BOTD;
    const float* w = Wr + (size_t)r * BOTD;
    float s = 0.f;
#pragma unroll
    for (int d = 0; d < BOTD; ++d) s += x[d] * w[d];
    out[i] = s;
}

// ---------------- router scores: rq[NTOK,48] @ rk[NSL,48]^T ----------------
__global__ void __launch_bounds__(256) scores_kernel(const float* __restrict__ rq,
                                                     const float* __restrict__ rk,
                                                     const float* __restrict__ log_rel,
                                                     float* __restrict__ scores) {
    constexpr int BT = 32, BSN = 128;
    __shared__ float s_rq[BT][RD + 1];
    __shared__ float s_rk[BSN][RD];
    const int t0 = blockIdx.y * BT, nb0 = blockIdx.x * BSN;
    const int tid = threadIdx.x;
    for (int i = tid; i < BT * RD; i += 256)
        s_rq[i / RD][i % RD] = rq[(size_t)(t0 + i / RD) * RD + i % RD];
    for (int i = tid; i < BSN * RD; i += 256)
        s_rk[i / RD][i % RD] = rk[(size_t)(nb0 + i / RD) * RD + i % RD];
    __syncthreads();
    const float sc = 0.14433756729740643f;  // 1/sqrt(48)
    const int tloc = tid & 31;
    const int nlo = (tid >> 5) * 16;
    for (int j = 0; j < 16; ++j) {
        int n = nlo + j;
        float s = 0.f;
#pragma unroll
        for (int r = 0; r < RD; ++r) s += s_rq[tloc][r] * s_rk[n][r];
        scores[(size_t)(t0 + tloc) * NSL + nb0 + n] = s * sc + log_rel[nb0 + n];
    }
}

// ---------------- per-token top-8 + attention + AV_d gather (shuffle reduce) ----------------
__global__ void __launch_bounds__(256) router_topk_kernel(
    const float* __restrict__ scores, const float* __restrict__ query,
    const float* __restrict__ aux_keys, const float* __restrict__ log_rel,
    const float* __restrict__ AVd, __nv_bfloat16* __restrict__ tb) {
    const int t = blockIdx.x, tid = threadIdx.x;
    const int w = tid >> 5, lane = tid & 31;
    __shared__ __align__(16) float ssc[NSL];
    __shared__ float sq[BOTD];
    __shared__ unsigned long long wred[8];
    __shared__ int sel[KS];
    __shared__ float slog[KS];

    ((float4*)ssc)[tid] = ((const float4*)(scores + (size_t)t * NSL))[tid];
    if (tid < BOTD) sq[tid] = query[(size_t)t * BOTD + tid];
    __syncthreads();

    for (int k = 0; k < KS; ++k) {
        unsigned long long best = 0ull;
#pragma unroll
        for (int j = 0; j < 4; ++j) {
            int idx = tid + j * 256;
            unsigned long long p = ((unsigned long long)fkey(ssc[idx]) << 32)
                                   | (unsigned)(NSL - 1 - idx);
            best = (p > best) ? p : best;
        }
#pragma unroll
        for (int o = 16; o > 0; o >>= 1) {
            unsigned long long q = __shfl_xor_sync(0xffffffffu, best, o);
            best = (q > best) ? q : best;
        }
        if (lane == 0) wred[w] = best;
        __syncthreads();
        if (tid < 8) {
            unsigned long long b = wred[tid];
#pragma unroll
            for (int o = 4; o > 0; o >>= 1) {
                unsigned long long q = __shfl_xor_sync(0xffu, b, o);
                b = (q > b) ? q : b;
            }
            if (tid == 0) {
                int idx = NSL - 1 - (int)(b & 0xFFFFFFFFu);
                sel[k] = idx;
                ssc[idx] = -INFINITY;
            }
        }
        __syncthreads();
    }

    // attention logits: 1 warp per selected slot
    {
        int idx = sel[w];
        const float* kr = aux_keys + (size_t)idx * BOTD;
        float s = sq[lane] * kr[lane] + sq[lane + 32] * kr[lane + 32];
#pragma unroll
        for (int o = 16; o > 0; o >>= 1) s += __shfl_xor_sync(0xffffffffu, s, o);
        if (lane == 0) slog[w] = s * 0.125f + log_rel[idx];
    }
    __syncthreads();

    // softmax over 8 (redundant across threads) + gather AV_d
    float m = slog[0];
#pragma unroll
    for (int k = 1; k < KS; ++k) m = fmaxf(m, slog[k]);
    float e[KS], sum = 0.f;
#pragma unroll
    for (int k = 0; k < KS; ++k) { e[k] = expf(slog[k] - m); sum += e[k]; }
    const float inv = 1.f / sum;
    float v = 0.f;
#pragma unroll
    for (int k = 0; k < KS; ++k) v += e[k] * inv * AVd[(size_t)sel[k] * VBD + tid];
    tb[(size_t)t * VBD + tid] = __float2bfloat16(v);
}

// ---------------- gate: global logvar mean -> per-token gate ----------------
__global__ void __launch_bounds__(1024) gate_kernel(const float* __restrict__ logvar,
                                                    const float* __restrict__ partial,
                                                    const float* __restrict__ bu2,
                                                    const float* __restrict__ gw1,
                                                    const float* __restrict__ gb,
                                                    float* __restrict__ gate) {
    __shared__ float red[1024];
    __shared__ float s_mean;
    const int tid = threadIdx.x;
    float s = 0.f;
    for (int i = tid; i < NTOK; i += 1024) s += logvar[i];
    red[tid] = s;
    __syncthreads();
    for (int st = 512; st > 0; st >>= 1) {
        if (tid < st) red[tid] += red[tid + st];
        __syncthreads();
    }
    if (tid == 0) s_mean = red[0] * (1.f / NTOK);
    __syncthreads();
    const float mean = s_mean;
    const float w1 = gw1[0], b = gb[0], b2 = bu2[0];
    for (int i = tid; i < NTOK; i += 1024) {
        float L = b2;
#pragma unroll
        for (int j = 0; j < 16; ++j) L += partial[j * NTOK + i];
        float nv = logvar[i] / (mean + 1e-6f);
        float u = fminf(fmaxf(nv * 0.5f + sigmoidf(L) * 2.5f, 0.f), 5.f);
        float un = fminf(fmaxf((u - 0.5f) * (1.f / 1.5f), 0.f), 1.f);
        float g = sigmoidf(w1 * un + b);
        gate[i] = (g < 0.05f) ? 0.f : g;
    }
}

// ---------------- launcher ----------------
extern "C" void kernel_launch(void* const* d_in, const int* in_sizes, int n_in,
                              void* d_out, int out_size) {
    const float* h        = (const float*)d_in[0];
    const float* Wq       = (const float*)d_in[1];
    const float* Wr       = (const float*)d_in[2];
    const float* aux_keys = (const float*)d_in[3];
    const float* aux_vals = (const float*)d_in[4];
    const float* Wvd      = (const float*)d_in[5];
    const float* Wvu      = (const float*)d_in[6];
    const float* Wu1      = (const float*)d_in[7];
    const float* bu1      = (const float*)d_in[8];
    const float* Wu2      = (const float*)d_in[9];
    const float* bu2      = (const float*)d_in[10];
    const float* gw1      = (const float*)d_in[11];
    const float* gb       = (const float*)d_in[12];
    const float* log_rel  = (const float*)d_in[13];
    float* out = (float*)d_out;

    __nv_bfloat16 *hb, *Wu1b, *Wqb, *avb, *Wvdb, *Wvub, *tb;
    float *query, *rq, *rk, *scores, *AVd, *AVd_part, *query_part, *partial, *logvar, *gate;
    cudaGetSymbolAddress((void**)&hb, g_hb);
    cudaGetSymbolAddress((void**)&Wu1b, g_Wu1b);
    cudaGetSymbolAddress((void**)&Wqb, g_Wqb);
    cudaGetSymbolAddress((void**)&avb, g_avb);
    cudaGetSymbolAddress((void**)&Wvdb, g_Wvdb);
    cudaGetSymbolAddress((void**)&Wvub, g_Wvub);
    cudaGetSymbolAddress((void**)&tb, g_tb);
    cudaGetSymbolAddress((void**)&query, g_query);
    cudaGetSymbolAddress((void**)&rq, g_rq);
    cudaGetSymbolAddress((void**)&rk, g_rk);
    cudaGetSymbolAddress((void**)&scores, g_scores);
    cudaGetSymbolAddress((void**)&AVd, g_AVd);
    cudaGetSymbolAddress((void**)&AVd_part, g_AVd_part);
    cudaGetSymbolAddress((void**)&query_part, g_query_part);
    cudaGetSymbolAddress((void**)&partial, g_partial);
    cudaGetSymbolAddress((void**)&logvar, g_logvar);
    cudaGetSymbolAddress((void**)&gate, g_gate);

    // dynamic smem sizes: 3-stage pipeline
    const int smem_128_128 = 3 * (128 + 128) * 40 * (int)sizeof(__nv_bfloat16);  // 61440
    const int smem_128_64  = 3 * (128 + 64) * 40 * (int)sizeof(__nv_bfloat16);   // 46080
    cudaFuncSetAttribute(gemm_tn<128, 128, 0>, cudaFuncAttributeMaxDynamicSharedMemorySize, smem_128_128);
    cudaFuncSetAttribute(gemm_tn<128, 128, 1>, cudaFuncAttributeMaxDynamicSharedMemorySize, smem_128_128);
    cudaFuncSetAttribute(gemm_tn<128, 128, 2>, cudaFuncAttributeMaxDynamicSharedMemorySize, smem_128_128);
    cudaFuncSetAttribute(gemm_tn<128, 64, 0>, cudaFuncAttributeMaxDynamicSharedMemorySize, smem_128_64);

    // h -> bf16 + per-token variance (fused)
    var_cvt_kernel<<<NTOK, 256>>>(h, hb, logvar);

    // all 5 weight converts in one launch (float4 granularity)
    {
        const int n0 = H4 * HIDD / 4, n1 = BOTD * HIDD / 4, n2 = NSL * HIDD / 4,
                  n3 = VBD * HIDD / 4, n4 = HIDD * VBD / 4;
        const int tot = n0 + n1 + n2 + n3 + n4;
        cvt_all_kernel<<<(tot + 255) / 256, 256>>>(
            Wu1, Wu1b, n0, Wq, Wqb, n1, aux_vals, avb, n2,
            Wvd, Wvdb, n3, Wvu, Wvub, n4);
    }

    // partial = Wu2 . gelu(h @ Wu1^T + bu1)   (big GEMM, fused epilogue, deterministic)
    gemm_tn<128, 128, 1><<<dim3(H4 / 128, NTOK / 128, 1), 256, smem_128_128>>>(
        hb, Wu1b, nullptr, NTOK, H4, HIDD, bu1, Wu2, partial);

    // rk = aux_keys @ Wr^T
    projr_kernel<<<(NSL * RD + 255) / 256, 256>>>(aux_keys, Wr, rk, NSL);

    // AV_d partials = aux_values @ Wvd^T, split-K=16 -> grid 2x8x16 = 256 blocks
    gemm_tn<128, 128, 0><<<dim3(VBD / 128, NSL / 128, SPLITK), 256, smem_128_128>>>(
        avb, Wvdb, AVd_part, NSL, VBD, HIDD, nullptr, nullptr, nullptr);

    // query partials = h @ Wq^T, split-K=16 -> grid 1x32x16 = 512 blocks
    gemm_tn<128, 64, 0><<<dim3(1, NTOK / 128, SPLITK), 256, smem_128_64>>>(
        hb, Wqb, query_part, NTOK, BOTD, HIDD, nullptr, nullptr, nullptr);

    // reduce both split-K partials (fixed order -> deterministic)
    {
        const int na = NSL * VBD, nb = NTOK * BOTD;
        reduce_parts_kernel<<<(na + nb + 255) / 256, 256>>>(
            AVd_part, AVd, na, query_part, query, nb);
    }

    // rq = query @ Wr^T
    projr_kernel<<<(NTOK * RD + 255) / 256, 256>>>(query, Wr, rq, NTOK);

    // router scores
    scores_kernel<<<dim3(NSL / 128, NTOK / 32), 256>>>(rq, rk, log_rel, scores);

    // top-8 + softmax + AV_d gather -> t (bf16)
    router_topk_kernel<<<NTOK, 256>>>(scores, query, aux_keys, log_rel, AVd, tb);

    // gate (needs global mean of logvar + learned)
    gate_kernel<<<1, 1024>>>(logvar, partial, bu2, gw1, gb, gate);

    // out = h + gate * (t @ Wvu^T)   (fused epilogue)
    gemm_tn<128, 128, 2><<<dim3(HIDD / 128, NTOK / 128, 1), 256, smem_128_128>>>(
        tb, Wvub, out, NTOK, HIDD, VBD, h, gate, nullptr);
}